// round 5
// baseline (speedup 1.0000x reference)
#include <cuda_runtime.h>

// out = noised + 0.1f * noise   (elementwise, fp32)
// N = 64*3*512*512 = 50,331,648 (divisible by 4)
// Pure HBM-streaming: 604 MB total traffic -> expect ~90 us at ~6.8 TB/s.

__global__ void __launch_bounds__(256)
gaussian_noise_add_kernel(const float4* __restrict__ noised,
                          const float4* __restrict__ noise,
                          float4* __restrict__ out,
                          int n4)
{
    int i = blockIdx.x * blockDim.x + threadIdx.x;
    if (i < n4) {
        float4 a = noised[i];
        float4 b = noise[i];
        float4 r;
        r.x = fmaf(0.1f, b.x, a.x);
        r.y = fmaf(0.1f, b.y, a.y);
        r.z = fmaf(0.1f, b.z, a.z);
        r.w = fmaf(0.1f, b.w, a.w);
        out[i] = r;
    }
}

// Scalar tail kernel (defensive; n is divisible by 4 for this problem so it
// launches with 0 blocks only when needed).
__global__ void gaussian_noise_tail_kernel(const float* __restrict__ noised,
                                           const float* __restrict__ noise,
                                           float* __restrict__ out,
                                           int start, int n)
{
    int i = start + blockIdx.x * blockDim.x + threadIdx.x;
    if (i < n) {
        out[i] = fmaf(0.1f, noise[i], noised[i]);
    }
}

extern "C" void kernel_launch(void* const* d_in, const int* in_sizes, int n_in,
                              void* d_out, int out_size)
{
    const float* noised = (const float*)d_in[0];
    const float* noise  = (const float*)d_in[1];
    float* out = (float*)d_out;
    int n = in_sizes[0];

    int n4 = n >> 2;
    if (n4 > 0) {
        int threads = 256;
        int blocks = (n4 + threads - 1) / threads;
        gaussian_noise_add_kernel<<<blocks, threads>>>(
            (const float4*)noised, (const float4*)noise, (float4*)out, n4);
    }
    int rem = n - (n4 << 2);
    if (rem > 0) {
        gaussian_noise_tail_kernel<<<1, 256>>>(noised, noise, out, n4 << 2, n);
    }
}